// round 10
// baseline (speedup 1.0000x reference)
#include <cuda_runtime.h>

#define N_NODES 100000
#define DIM     128
#define N_EDGES 1600000
#define ALPHA   4

// ---------------- device scratch (static globals; no runtime alloc) ----------------
__device__ int   g_stride;                       // 1 = int32 edge_index, 2 = int64 (low word)
__device__ float g_dinv[ALPHA * N_NODES];
__device__ int   g_cnt [ALPHA * N_NODES];
__device__ int   g_offs[ALPHA * (N_NODES + 1)];
__device__ int   g_curs[ALPHA * N_NODES];
__device__ int2  g_edge[ALPHA * N_EDGES];        // CSC: {src row, w/norm bits} grouped by dest
__device__ float g_hw  [(size_t)N_NODES * DIM];  // h @ W^T scratch (51.2 MB, L2-resident)

// ---------------- dtype detection: int64 edge_index has zero high words ----------------
__global__ void detect_kernel(const int* __restrict__ ei32)
{
    if (threadIdx.x == 0 && blockIdx.x == 0) {
        bool all_zero = true;
        #pragma unroll
        for (int i = 1; i < 64; i += 2) all_zero = all_zero && (ei32[i] == 0);
        g_stride = all_zero ? 2 : 1;   // values < 2^31, nonneg: high word 0 iff int64
    }
}

// ---------------- zero cnt ----------------
__global__ void zero_kernel()
{
    int i = blockIdx.x * blockDim.x + threadIdx.x;
    if (i < ALPHA * N_NODES) g_cnt[i] = 0;
}

// ---------------- count histogram over all 4 edge sets (int atomics only) ----------------
__global__ void hist_kernel(const int* __restrict__ ei32)
{
    int idx = blockIdx.x * blockDim.x + threadIdx.x;
    if (idx >= ALPHA * N_EDGES) return;
    int l = idx / N_EDGES;
    int e = idx - l * N_EDGES;
    int s = g_stride;
    int col = ei32[(size_t)(l * 2 * N_EDGES + N_EDGES + e) * s];
    if ((unsigned)col >= N_NODES) return;        // safety: never OOB
    atomicAdd(&g_cnt[l * N_NODES + col], 1);
}

// ---------------- exclusive scan of cnt -> offs (and cursor copy); one block per layer ----------------
__global__ void scan_kernel()
{
    int layer = blockIdx.x;
    const int* c = g_cnt + layer * N_NODES;
    int* o   = g_offs + layer * (N_NODES + 1);
    int* cur = g_curs + layer * N_NODES;

    __shared__ int warp_sums[32];
    __shared__ int s_carry;
    int tid  = threadIdx.x;
    int lane = tid & 31;
    int wid  = tid >> 5;
    if (tid == 0) s_carry = 0;
    __syncthreads();

    for (int base = 0; base < N_NODES; base += 1024) {
        int i = base + tid;
        int v = (i < N_NODES) ? c[i] : 0;
        int x = v;
        #pragma unroll
        for (int d = 1; d < 32; d <<= 1) {
            int t = __shfl_up_sync(0xffffffffu, x, d);
            if (lane >= d) x += t;
        }
        if (lane == 31) warp_sums[wid] = x;
        __syncthreads();
        if (wid == 0) {
            int s = warp_sums[lane];
            #pragma unroll
            for (int d = 1; d < 32; d <<= 1) {
                int t = __shfl_up_sync(0xffffffffu, s, d);
                if (lane >= d) s += t;
            }
            warp_sums[lane] = s;
        }
        __syncthreads();
        int incl = x + ((wid > 0) ? warp_sums[wid - 1] : 0) + s_carry;
        if (i < N_NODES) { o[i] = incl - v; cur[i] = incl - v; }
        __syncthreads();
        if (tid == 1023) s_carry = incl;
        __syncthreads();
    }
    if (tid == 0) o[N_NODES] = s_carry;
}

// ---------------- scatter edges into CSC buckets: raw (row, w) -- no dinv dependency ----------------
__global__ void build_kernel(const int* __restrict__ ei32, const float* __restrict__ ea)
{
    int idx = blockIdx.x * blockDim.x + threadIdx.x;
    if (idx >= ALPHA * N_EDGES) return;
    int l = idx / N_EDGES;
    int e = idx - l * N_EDGES;
    int s = g_stride;
    int row = ei32[(size_t)(l * 2 * N_EDGES + e) * s];
    int col = ei32[(size_t)(l * 2 * N_EDGES + N_EDGES + e) * s];
    if ((unsigned)row >= N_NODES || (unsigned)col >= N_NODES) return;  // safety
    float w = ea[(size_t)l * N_EDGES + e];
    int pos = atomicAdd(&g_curs[l * N_NODES + col], 1);
    g_edge[(size_t)l * N_EDGES + pos] = make_int2(row, __float_as_int(w));
}

// ---------------- per-node: deg = segment sum of w (coalesced, no atomics); dinv = rsqrt ----------------
__global__ void __launch_bounds__(256) deg_dinv_kernel()
{
    int gid  = blockIdx.x * 8 + (threadIdx.x >> 5);
    int lane = threadIdx.x & 31;
    if (gid >= ALPHA * N_NODES) return;
    int layer = gid / N_NODES;
    int node  = gid - layer * N_NODES;

    const int*  offs  = g_offs + layer * (N_NODES + 1);
    const int2* edges = g_edge + (size_t)layer * N_EDGES;
    int s = offs[node], e = offs[node + 1];

    float sum = 0.f;
    for (int i = s + lane; i < e; i += 32)
        sum += __int_as_float(edges[i].y);
    #pragma unroll
    for (int d = 16; d; d >>= 1) sum += __shfl_xor_sync(0xffffffffu, sum, d);
    if (lane == 0) g_dinv[gid] = (sum > 0.f) ? rsqrtf(sum) : 0.f;
}

// ---------------- per-node fixup: w -> dinv[row] * w * dinv[col] ----------------
__global__ void __launch_bounds__(256) fixup_kernel()
{
    int gid  = blockIdx.x * 8 + (threadIdx.x >> 5);
    int lane = threadIdx.x & 31;
    if (gid >= ALPHA * N_NODES) return;
    int layer = gid / N_NODES;
    int node  = gid - layer * N_NODES;

    const int*   offs  = g_offs + layer * (N_NODES + 1);
    int2*        edges = g_edge + (size_t)layer * N_EDGES;
    const float* dinvl = g_dinv + layer * N_NODES;
    int s = offs[node], e = offs[node + 1];

    float dc = g_dinv[gid];
    for (int i = s + lane; i < e; i += 32) {
        int2 p = edges[i];
        float nm = dinvl[p.x] * __int_as_float(p.y) * dc;
        edges[i] = make_int2(p.x, __float_as_int(nm));
    }
}

// ---------------- GEMM via packed fma.rn.f32x2 (FFMA2): 2 FMA per fma-pipe slot ----------------
// out[n,d] = sum_k A[n,k] * W[d,k]  (+bias, relu if mode==1; mode 0 writes g_hw)
// 64 rows/block, 256 threads: 8 rows/warp, 4 cols/lane (2 f32x2 col-pairs).
// SMEM: Ws [128][132] f32 transposed; Hd [128][65] float2 with h duplicated into both halves
// so no per-iteration packing MOVs are needed.
#define GEMM_ROWS 64
#define GEMM_SMEM (128 * 132 * 4 + 128 * 65 * 8)

__device__ __forceinline__ void ffma2(unsigned long long& d,
                                      unsigned long long a, unsigned long long b)
{
    asm("fma.rn.f32x2 %0, %1, %2, %0;" : "+l"(d) : "l"(a), "l"(b));
}

__global__ void __launch_bounds__(256) gemm_kernel(
    const float* __restrict__ A, const float* __restrict__ W,
    const float* __restrict__ bias, float* __restrict__ C,
    int nrows, int mode)
{
    extern __shared__ float sm[];
    float*  Ws = sm;                               // [128][132]  Ws[k*132+d] = W[d][k]
    float2* Hd = (float2*)(sm + 128 * 132);        // [128][65]   Hd[k*65+r] = (h, h)

    int tid  = threadIdx.x;
    int lane = tid & 31;
    int warp = tid >> 5;
    int row0 = blockIdx.x * GEMM_ROWS;

    // load W transposed into smem (coalesced global reads)
    for (int idx = tid; idx < 128 * 128; idx += 256) {
        int d = idx >> 7, k = idx & 127;
        Ws[k * 132 + d] = W[idx];
    }
    // load H tile duplicated: Hd[k][r] = (A[row0+r][k], same). Coalesced over k.
    for (int idx = tid; idx < GEMM_ROWS * 128; idx += 256) {
        int r = idx >> 7, k = idx & 127;
        int grow = row0 + r;
        float v = (grow < nrows) ? A[(size_t)grow * DIM + k] : 0.f;
        Hd[k * 65 + r] = make_float2(v, v);
    }
    __syncthreads();

    unsigned long long acc[8][2];
    #pragma unroll
    for (int r = 0; r < 8; r++) { acc[r][0] = 0ull; acc[r][1] = 0ull; }

    unsigned ws_addr = (unsigned)__cvta_generic_to_shared(Ws) + lane * 16;
    unsigned hd_addr = (unsigned)__cvta_generic_to_shared(Hd) + (warp * 8) * 8;

    #pragma unroll 2
    for (int k = 0; k < 128; k++) {
        unsigned long long w01, w23;
        asm volatile("ld.shared.v2.b64 {%0, %1}, [%2];"
                     : "=l"(w01), "=l"(w23) : "r"(ws_addr + k * 528));
        #pragma unroll
        for (int r = 0; r < 8; r++) {
            unsigned long long hp;   // (h, h) duplicated pair, warp-broadcast LDS.64
            asm volatile("ld.shared.b64 %0, [%1];"
                         : "=l"(hp) : "r"(hd_addr + k * 520 + r * 8));
            ffma2(acc[r][0], hp, w01);
            ffma2(acc[r][1], hp, w23);
        }
    }

    float4 bv = make_float4(0.f, 0.f, 0.f, 0.f);
    if (mode == 1) bv = *(const float4*)(bias + lane * 4);

    #pragma unroll
    for (int r = 0; r < 8; r++) {
        int grow = row0 + warp * 8 + r;
        if (grow < nrows) {
            float4 o;
            o.x = __uint_as_float((unsigned)(acc[r][0] & 0xffffffffull));
            o.y = __uint_as_float((unsigned)(acc[r][0] >> 32));
            o.z = __uint_as_float((unsigned)(acc[r][1] & 0xffffffffull));
            o.w = __uint_as_float((unsigned)(acc[r][1] >> 32));
            float* dst;
            if (mode == 1) {
                o.x = fmaxf(o.x + bv.x, 0.f);
                o.y = fmaxf(o.y + bv.y, 0.f);
                o.z = fmaxf(o.z + bv.z, 0.f);
                o.w = fmaxf(o.w + bv.w, 0.f);
                dst = C;
            } else {
                dst = g_hw;
            }
            *(float4*)(dst + (size_t)grow * DIM + lane * 4) = o;
        }
    }
}

// ---------------- pull aggregation: one warp per destination node, fused bias + relu ----------------
// 2-wide edge unroll with dual accumulators -> 2 outstanding L2 gathers per warp.
__global__ void __launch_bounds__(256) pull_kernel(
    int layer, const float* __restrict__ bias, float* __restrict__ out)
{
    int node = blockIdx.x * 8 + (threadIdx.x >> 5);
    int lane = threadIdx.x & 31;
    if (node >= N_NODES) return;

    const int*  offs  = g_offs + layer * (N_NODES + 1);
    const int2* edges = g_edge + (size_t)layer * N_EDGES;

    int e = offs[node], end = offs[node + 1];
    float4 a0 = make_float4(0.f, 0.f, 0.f, 0.f);
    float4 a1 = make_float4(0.f, 0.f, 0.f, 0.f);

    for (; e + 1 < end; e += 2) {
        int2 p0 = edges[e];
        int2 p1 = edges[e + 1];
        float4 v0 = *(const float4*)(g_hw + (size_t)p0.x * DIM + lane * 4);
        float4 v1 = *(const float4*)(g_hw + (size_t)p1.x * DIM + lane * 4);
        float n0 = __int_as_float(p0.y);
        float n1 = __int_as_float(p1.y);
        a0.x = fmaf(n0, v0.x, a0.x);  a1.x = fmaf(n1, v1.x, a1.x);
        a0.y = fmaf(n0, v0.y, a0.y);  a1.y = fmaf(n1, v1.y, a1.y);
        a0.z = fmaf(n0, v0.z, a0.z);  a1.z = fmaf(n1, v1.z, a1.z);
        a0.w = fmaf(n0, v0.w, a0.w);  a1.w = fmaf(n1, v1.w, a1.w);
    }
    if (e < end) {
        int2 p0 = edges[e];
        float4 v0 = *(const float4*)(g_hw + (size_t)p0.x * DIM + lane * 4);
        float n0 = __int_as_float(p0.y);
        a0.x = fmaf(n0, v0.x, a0.x);
        a0.y = fmaf(n0, v0.y, a0.y);
        a0.z = fmaf(n0, v0.z, a0.z);
        a0.w = fmaf(n0, v0.w, a0.w);
    }

    float4 b = *(const float4*)(bias + lane * 4);
    float4 o;
    o.x = fmaxf(a0.x + a1.x + b.x, 0.f);
    o.y = fmaxf(a0.y + a1.y + b.y, 0.f);
    o.z = fmaxf(a0.z + a1.z + b.z, 0.f);
    o.w = fmaxf(a0.w + a1.w + b.w, 0.f);
    *(float4*)(out + (size_t)node * DIM + lane * 4) = o;
}

// ---------------- host launch ----------------
extern "C" void kernel_launch(void* const* d_in, const int* in_sizes, int n_in,
                              void* d_out, int out_size)
{
    const float* x      = (const float*)d_in[0];
    const int*   ei32   = (const int*)d_in[1];
    const float* ea     = (const float*)d_in[2];
    const float* lin_w  = (const float*)d_in[3];
    const float* lin_b  = (const float*)d_in[4];
    const float* conv_w = (const float*)d_in[5];
    const float* conv_b = (const float*)d_in[6];
    float*       out    = (float*)d_out;

    // One-time host resources (no device memory involved; identical work every call).
    static cudaStream_t s_side = nullptr;
    static cudaEvent_t  ev_fork = nullptr, ev_join = nullptr;
    if (s_side == nullptr) {
        cudaStreamCreateWithFlags(&s_side, cudaStreamNonBlocking);
        cudaEventCreateWithFlags(&ev_fork, cudaEventDisableTiming);
        cudaEventCreateWithFlags(&ev_join, cudaEventDisableTiming);
        cudaFuncSetAttribute(gemm_kernel, cudaFuncAttributeMaxDynamicSharedMemorySize, GEMM_SMEM);
    }

    int gblocks = (N_NODES + GEMM_ROWS - 1) / GEMM_ROWS;
    int pblocks = (N_NODES + 7) / 8;
    int wblocks = (ALPHA * N_NODES + 7) / 8;   // warp-per-node kernels
    int n  = ALPHA * N_NODES;
    int ne = ALPHA * N_EDGES;

    // ---- fork: graph preprocessing on side stream, parallel to first two GEMMs ----
    cudaEventRecord(ev_fork, 0);
    cudaStreamWaitEvent(s_side, ev_fork, 0);

    detect_kernel<<<1, 32, 0, s_side>>>(ei32);
    zero_kernel<<<(n + 255) / 256, 256, 0, s_side>>>();
    hist_kernel<<<(ne + 255) / 256, 256, 0, s_side>>>(ei32);
    scan_kernel<<<ALPHA, 1024, 0, s_side>>>();
    build_kernel<<<(ne + 255) / 256, 256, 0, s_side>>>(ei32, ea);
    deg_dinv_kernel<<<wblocks, 256, 0, s_side>>>();
    fixup_kernel<<<wblocks, 256, 0, s_side>>>();
    cudaEventRecord(ev_join, s_side);

    // ---- main stream: h0 = relu(x @ lin_w^T + lin_b), then hw0 = h0 @ conv_w0^T ----
    gemm_kernel<<<gblocks, 256, GEMM_SMEM>>>(x, lin_w, lin_b, out, N_NODES, 1);
    gemm_kernel<<<gblocks, 256, GEMM_SMEM>>>(out, conv_w, nullptr, nullptr, N_NODES, 0);

    // join: pull needs the CSC with final norms
    cudaStreamWaitEvent(0, ev_join, 0);

    for (int i = 0; i < ALPHA; i++) {
        float* h_ot = out + (size_t)(i + 1) * N_NODES * DIM;
        // h_{i+1}[n] = relu( sum_in-edges norm * hw[row] + conv_b[i] )
        pull_kernel<<<pblocks, 256>>>(i, conv_b + (size_t)i * DIM, h_ot);
        // hw_{i+1} = h_{i+1} @ conv_w[i+1]^T (skip after last layer)
        if (i + 1 < ALPHA) {
            gemm_kernel<<<gblocks, 256, GEMM_SMEM>>>(
                h_ot, conv_w + (size_t)(i + 1) * DIM * DIM, nullptr, nullptr, N_NODES, 0);
        }
    }
}

// round 14
// speedup vs baseline: 1.3038x; 1.3038x over previous
#include <cuda_runtime.h>

#define N_NODES 100000
#define DIM     128
#define N_EDGES 1600000
#define ALPHA   4

#define SCAN_BLK   1024
#define BLKS_PER_L ((N_NODES + SCAN_BLK - 1) / SCAN_BLK)   // 98

// ---------------- device scratch (static globals; no runtime alloc) ----------------
__device__ int   g_stride;                       // 1 = int32 edge_index, 2 = int64 (low word)
__device__ float g_deg [ALPHA * N_NODES];
__device__ float g_dinv[ALPHA * N_NODES];
__device__ int   g_cnt [ALPHA * N_NODES];
__device__ int   g_offs[ALPHA * (N_NODES + 1)];
__device__ int   g_curs[ALPHA * N_NODES];
__device__ int   g_bsum[ALPHA * BLKS_PER_L];     // per-block sums for parallel scan
__device__ int   g_boff[ALPHA * BLKS_PER_L];     // scanned block offsets
__device__ int2  g_edge[ALPHA * N_EDGES];        // CSC: {src row, norm bits} grouped by dest
__device__ float g_hw  [(size_t)N_NODES * DIM];  // h @ W^T scratch (51.2 MB, L2-resident)

// ---------------- dtype detection: int64 edge_index has zero high words ----------------
__global__ void detect_kernel(const int* __restrict__ ei32)
{
    if (threadIdx.x == 0 && blockIdx.x == 0) {
        bool all_zero = true;
        #pragma unroll
        for (int i = 1; i < 64; i += 2) all_zero = all_zero && (ei32[i] == 0);
        g_stride = all_zero ? 2 : 1;   // values < 2^31, nonneg: high word 0 iff int64
    }
}

// ---------------- zero deg/cnt ----------------
__global__ void zero_kernel()
{
    int i = blockIdx.x * blockDim.x + threadIdx.x;
    if (i < ALPHA * N_NODES) { g_deg[i] = 0.f; g_cnt[i] = 0; }
}

// ---------------- weighted degree + count histogram over all 4 edge sets ----------------
__global__ void hist_kernel(const int* __restrict__ ei32, const float* __restrict__ ea)
{
    int idx = blockIdx.x * blockDim.x + threadIdx.x;
    if (idx >= ALPHA * N_EDGES) return;
    int l = idx / N_EDGES;
    int e = idx - l * N_EDGES;
    int s = g_stride;
    int col = ei32[(size_t)(l * 2 * N_EDGES + N_EDGES + e) * s];
    if ((unsigned)col >= N_NODES) return;        // safety: never OOB
    float w = ea[(size_t)l * N_EDGES + e];
    atomicAdd(&g_deg[l * N_NODES + col], w);
    atomicAdd(&g_cnt[l * N_NODES + col], 1);
}

// ---------------- dinv = deg > 0 ? rsqrt(deg) : 0 ----------------
__global__ void dinv_kernel()
{
    int i = blockIdx.x * blockDim.x + threadIdx.x;
    if (i >= ALPHA * N_NODES) return;
    float d = g_deg[i];
    g_dinv[i] = (d > 0.f) ? rsqrtf(d) : 0.f;
}

// ---------------- parallel scan, phase A: per-block exclusive scan + block sums ----------------
__global__ void __launch_bounds__(SCAN_BLK) scanA_kernel()
{
    int layer = blockIdx.x / BLKS_PER_L;
    int blk   = blockIdx.x - layer * BLKS_PER_L;
    int tid   = threadIdx.x;
    int lane  = tid & 31;
    int wid   = tid >> 5;
    int i     = blk * SCAN_BLK + tid;

    __shared__ int warp_sums[32];

    int v = (i < N_NODES) ? g_cnt[layer * N_NODES + i] : 0;
    int x = v;
    #pragma unroll
    for (int d = 1; d < 32; d <<= 1) {
        int t = __shfl_up_sync(0xffffffffu, x, d);
        if (lane >= d) x += t;
    }
    if (lane == 31) warp_sums[wid] = x;
    __syncthreads();
    if (wid == 0) {
        int s = warp_sums[lane];
        #pragma unroll
        for (int d = 1; d < 32; d <<= 1) {
            int t = __shfl_up_sync(0xffffffffu, s, d);
            if (lane >= d) s += t;
        }
        warp_sums[lane] = s;
    }
    __syncthreads();
    int incl = x + ((wid > 0) ? warp_sums[wid - 1] : 0);
    if (i < N_NODES) g_offs[layer * (N_NODES + 1) + i] = incl - v;   // local exclusive
    if (tid == SCAN_BLK - 1) g_bsum[blockIdx.x] = incl;
}

// ---------------- phase B: scan the 98 block sums per layer (one warp per layer) ----------------
__global__ void scanB_kernel()
{
    int layer = blockIdx.x;
    int lane  = threadIdx.x;   // 32 threads
    int carry = 0;
    for (int base = 0; base < BLKS_PER_L; base += 32) {
        int idx = base + lane;
        int v = (idx < BLKS_PER_L) ? g_bsum[layer * BLKS_PER_L + idx] : 0;
        int x = v;
        #pragma unroll
        for (int d = 1; d < 32; d <<= 1) {
            int t = __shfl_up_sync(0xffffffffu, x, d);
            if (lane >= d) x += t;
        }
        if (idx < BLKS_PER_L) g_boff[layer * BLKS_PER_L + idx] = carry + x - v;
        carry += __shfl_sync(0xffffffffu, x, 31);
    }
    if (lane == 0) g_offs[layer * (N_NODES + 1) + N_NODES] = carry;
}

// ---------------- phase C: add block offsets, copy cursors ----------------
__global__ void __launch_bounds__(SCAN_BLK) scanC_kernel()
{
    int layer = blockIdx.x / BLKS_PER_L;
    int blk   = blockIdx.x - layer * BLKS_PER_L;
    int i     = blk * SCAN_BLK + threadIdx.x;
    if (i >= N_NODES) return;
    int off = g_offs[layer * (N_NODES + 1) + i] + g_boff[blockIdx.x];
    g_offs[layer * (N_NODES + 1) + i] = off;
    g_curs[layer * N_NODES + i] = off;
}

// ---------------- scatter edges into CSC buckets (packed int2 payload) ----------------
__global__ void build_kernel(const int* __restrict__ ei32, const float* __restrict__ ea)
{
    int idx = blockIdx.x * blockDim.x + threadIdx.x;
    if (idx >= ALPHA * N_EDGES) return;
    int l = idx / N_EDGES;
    int e = idx - l * N_EDGES;
    int s = g_stride;
    int row = ei32[(size_t)(l * 2 * N_EDGES + e) * s];
    int col = ei32[(size_t)(l * 2 * N_EDGES + N_EDGES + e) * s];
    if ((unsigned)row >= N_NODES || (unsigned)col >= N_NODES) return;  // safety
    float w = ea[(size_t)l * N_EDGES + e];
    float nm = g_dinv[l * N_NODES + row] * w * g_dinv[l * N_NODES + col];
    int pos = atomicAdd(&g_curs[l * N_NODES + col], 1);
    g_edge[(size_t)l * N_EDGES + pos] = make_int2(row, __float_as_int(nm));
}

// ---------------- GEMM: out[n,d] = sum_k A[n,k] * W[d,k]  (+bias, relu if mode==1) ----------------
// mode 0: write g_hw (no bias/relu). mode 1: write C with bias + relu.
// 64 rows/block, 256 threads: 8 rows/warp, 4 cols/lane. W transposed in smem (pitch 132).
#define GEMM_ROWS 64
#define GEMM_SMEM ((128 * 132 + GEMM_ROWS * 128) * 4)

__global__ void __launch_bounds__(256) gemm_kernel(
    const float* __restrict__ A, const float* __restrict__ W,
    const float* __restrict__ bias, float* __restrict__ C,
    int nrows, int mode)
{
    extern __shared__ float sm[];
    float* Ws = sm;                 // [128][132]  Ws[k*132+d] = W[d][k]
    float* Hs = sm + 128 * 132;     // [64][128]

    int tid  = threadIdx.x;
    int lane = tid & 31;
    int warp = tid >> 5;
    int row0 = blockIdx.x * GEMM_ROWS;

    // load W transposed into smem (coalesced global reads)
    for (int idx = tid; idx < 128 * 128; idx += 256) {
        int d = idx >> 7, k = idx & 127;
        Ws[k * 132 + d] = W[idx];
    }
    // load H tile (float4 coalesced), zero-fill past nrows
    for (int idx = tid; idx < GEMM_ROWS * 32; idx += 256) {
        int r  = idx >> 5;
        int c4 = idx & 31;
        int grow = row0 + r;
        float4 v = make_float4(0.f, 0.f, 0.f, 0.f);
        if (grow < nrows) v = ((const float4*)(A + (size_t)grow * DIM))[c4];
        ((float4*)(Hs + r * DIM))[c4] = v;
    }
    __syncthreads();

    float acc[8][4];
    #pragma unroll
    for (int r = 0; r < 8; r++) { acc[r][0]=0.f; acc[r][1]=0.f; acc[r][2]=0.f; acc[r][3]=0.f; }

    const float* hbase = Hs + (warp * 8) * DIM;
    #pragma unroll 2
    for (int k = 0; k < 128; k++) {
        float4 wv = *(const float4*)&Ws[k * 132 + lane * 4];
        #pragma unroll
        for (int r = 0; r < 8; r++) {
            float hv = hbase[r * DIM + k];
            acc[r][0] = fmaf(hv, wv.x, acc[r][0]);
            acc[r][1] = fmaf(hv, wv.y, acc[r][1]);
            acc[r][2] = fmaf(hv, wv.z, acc[r][2]);
            acc[r][3] = fmaf(hv, wv.w, acc[r][3]);
        }
    }

    float4 bv = make_float4(0.f, 0.f, 0.f, 0.f);
    if (mode == 1) bv = *(const float4*)(bias + lane * 4);

    #pragma unroll
    for (int r = 0; r < 8; r++) {
        int grow = row0 + warp * 8 + r;
        if (grow < nrows) {
            float4 o;
            o.x = acc[r][0]; o.y = acc[r][1]; o.z = acc[r][2]; o.w = acc[r][3];
            float* dst;
            if (mode == 1) {
                o.x = fmaxf(o.x + bv.x, 0.f);
                o.y = fmaxf(o.y + bv.y, 0.f);
                o.z = fmaxf(o.z + bv.z, 0.f);
                o.w = fmaxf(o.w + bv.w, 0.f);
                dst = C;
            } else {
                dst = g_hw;
            }
            *(float4*)(dst + (size_t)grow * DIM + lane * 4) = o;
        }
    }
}

// ---------------- pull aggregation: one warp per destination node, fused bias + relu ----------------
// 2-wide edge unroll with dual accumulators -> 2 outstanding L2 gathers per warp.
__global__ void __launch_bounds__(256) pull_kernel(
    int layer, const float* __restrict__ bias, float* __restrict__ out)
{
    int node = blockIdx.x * 8 + (threadIdx.x >> 5);
    int lane = threadIdx.x & 31;
    if (node >= N_NODES) return;

    const int*  offs  = g_offs + layer * (N_NODES + 1);
    const int2* edges = g_edge + (size_t)layer * N_EDGES;

    int e = offs[node], end = offs[node + 1];
    float4 a0 = make_float4(0.f, 0.f, 0.f, 0.f);
    float4 a1 = make_float4(0.f, 0.f, 0.f, 0.f);

    for (; e + 1 < end; e += 2) {
        int2 p0 = edges[e];
        int2 p1 = edges[e + 1];
        float4 v0 = *(const float4*)(g_hw + (size_t)p0.x * DIM + lane * 4);
        float4 v1 = *(const float4*)(g_hw + (size_t)p1.x * DIM + lane * 4);
        float n0 = __int_as_float(p0.y);
        float n1 = __int_as_float(p1.y);
        a0.x = fmaf(n0, v0.x, a0.x);  a1.x = fmaf(n1, v1.x, a1.x);
        a0.y = fmaf(n0, v0.y, a0.y);  a1.y = fmaf(n1, v1.y, a1.y);
        a0.z = fmaf(n0, v0.z, a0.z);  a1.z = fmaf(n1, v1.z, a1.z);
        a0.w = fmaf(n0, v0.w, a0.w);  a1.w = fmaf(n1, v1.w, a1.w);
    }
    if (e < end) {
        int2 p0 = edges[e];
        float4 v0 = *(const float4*)(g_hw + (size_t)p0.x * DIM + lane * 4);
        float n0 = __int_as_float(p0.y);
        a0.x = fmaf(n0, v0.x, a0.x);
        a0.y = fmaf(n0, v0.y, a0.y);
        a0.z = fmaf(n0, v0.z, a0.z);
        a0.w = fmaf(n0, v0.w, a0.w);
    }

    float4 b = *(const float4*)(bias + lane * 4);
    float4 o;
    o.x = fmaxf(a0.x + a1.x + b.x, 0.f);
    o.y = fmaxf(a0.y + a1.y + b.y, 0.f);
    o.z = fmaxf(a0.z + a1.z + b.z, 0.f);
    o.w = fmaxf(a0.w + a1.w + b.w, 0.f);
    *(float4*)(out + (size_t)node * DIM + lane * 4) = o;
}

// ---------------- host launch ----------------
extern "C" void kernel_launch(void* const* d_in, const int* in_sizes, int n_in,
                              void* d_out, int out_size)
{
    const float* x      = (const float*)d_in[0];
    const int*   ei32   = (const int*)d_in[1];
    const float* ea     = (const float*)d_in[2];
    const float* lin_w  = (const float*)d_in[3];
    const float* lin_b  = (const float*)d_in[4];
    const float* conv_w = (const float*)d_in[5];
    const float* conv_b = (const float*)d_in[6];
    float*       out    = (float*)d_out;

    // One-time host resources (no device memory involved; identical work every call).
    static cudaStream_t s_side = nullptr;
    static cudaEvent_t  ev_fork = nullptr, ev_join = nullptr;
    if (s_side == nullptr) {
        cudaStreamCreateWithFlags(&s_side, cudaStreamNonBlocking);
        cudaEventCreateWithFlags(&ev_fork, cudaEventDisableTiming);
        cudaEventCreateWithFlags(&ev_join, cudaEventDisableTiming);
        cudaFuncSetAttribute(gemm_kernel, cudaFuncAttributeMaxDynamicSharedMemorySize, GEMM_SMEM);
    }

    int gblocks = (N_NODES + GEMM_ROWS - 1) / GEMM_ROWS;
    int pblocks = (N_NODES + 7) / 8;
    int n  = ALPHA * N_NODES;
    int ne = ALPHA * N_EDGES;

    // ---- fork: graph preprocessing on side stream, parallel to first two GEMMs ----
    cudaEventRecord(ev_fork, 0);
    cudaStreamWaitEvent(s_side, ev_fork, 0);

    detect_kernel<<<1, 32, 0, s_side>>>(ei32);
    zero_kernel<<<(n + 255) / 256, 256, 0, s_side>>>();
    hist_kernel<<<(ne + 255) / 256, 256, 0, s_side>>>(ei32, ea);
    dinv_kernel<<<(n + 255) / 256, 256, 0, s_side>>>();
    scanA_kernel<<<ALPHA * BLKS_PER_L, SCAN_BLK, 0, s_side>>>();
    scanB_kernel<<<ALPHA, 32, 0, s_side>>>();
    scanC_kernel<<<ALPHA * BLKS_PER_L, SCAN_BLK, 0, s_side>>>();
    build_kernel<<<(ne + 255) / 256, 256, 0, s_side>>>(ei32, ea);
    cudaEventRecord(ev_join, s_side);

    // ---- main stream: h0 = relu(x @ lin_w^T + lin_b), then hw0 = h0 @ conv_w0^T ----
    gemm_kernel<<<gblocks, 256, GEMM_SMEM>>>(x, lin_w, lin_b, out, N_NODES, 1);
    gemm_kernel<<<gblocks, 256, GEMM_SMEM>>>(out, conv_w, nullptr, nullptr, N_NODES, 0);

    // join: pull needs the CSC with final norms
    cudaStreamWaitEvent(0, ev_join, 0);

    for (int i = 0; i < ALPHA; i++) {
        float* h_ot = out + (size_t)(i + 1) * N_NODES * DIM;
        // h_{i+1}[n] = relu( sum_in-edges norm * hw[row] + conv_b[i] )
        pull_kernel<<<pblocks, 256>>>(i, conv_b + (size_t)i * DIM, h_ot);
        // hw_{i+1} = h_{i+1} @ conv_w[i+1]^T (skip after last layer)
        if (i + 1 < ALPHA) {
            gemm_kernel<<<gblocks, 256, GEMM_SMEM>>>(
                h_ot, conv_w + (size_t)(i + 1) * DIM * DIM, nullptr, nullptr, N_NODES, 0);
        }
    }
}